// round 15
// baseline (speedup 1.0000x reference)
#include <cuda_runtime.h>
#include <cuda_bf16.h>
#include <math.h>

#define N_POINTS 8192
#define TI 1024              // i-range per pair block
#define TJ 32                // j-range per pair block
#define THREADS 256
#define IPT 4                // i's per thread (contiguous)
#define NJC (N_POINTS / TJ)  // 256 j-chunks
#define PAIR_TILES 1152      // sum_{a=0}^{7} (256 - 32a)
#define GRID PAIR_TILES

typedef unsigned long long u64;

// Scratch: one slot per block + completion counter (int atomics only).
__device__ double g_pair_partial[GRID];
__device__ float  g_s1_partial[GRID];
__device__ float  g_s2_partial[GRID];
__device__ int    g_done = 0;

__device__ __forceinline__ float frcp_approx(float x) {
    float y;
    asm("rcp.approx.f32 %0, %1;" : "=f"(y) : "f"(x));
    return y;
}

// ---- packed f32x2 helpers (sm_103a; PTX-only, ptxas won't auto-fuse) ----
__device__ __forceinline__ u64 pack2(float lo, float hi) {
    u64 r; asm("mov.b64 %0, {%1, %2};" : "=l"(r) : "f"(lo), "f"(hi)); return r;
}
__device__ __forceinline__ void unpack2(u64 v, float& lo, float& hi) {
    asm("mov.b64 {%0, %1}, %2;" : "=f"(lo), "=f"(hi) : "l"(v));
}
__device__ __forceinline__ u64 fma2(u64 a, u64 b, u64 c) {
    u64 d; asm("fma.rn.f32x2 %0, %1, %2, %3;" : "=l"(d) : "l"(a), "l"(b), "l"(c)); return d;
}
__device__ __forceinline__ u64 add2(u64 a, u64 b) {
    u64 d; asm("add.rn.f32x2 %0, %1, %2;" : "=l"(d) : "l"(a), "l"(b)); return d;
}
__device__ __forceinline__ u64 mul2(u64 a, u64 b) {
    u64 d; asm("mul.rn.f32x2 %0, %1, %2;" : "=l"(d) : "l"(a), "l"(b)); return d;
}

// Block reduce; full sum valid on thread 0 only. All threads must call.
__device__ __forceinline__ float block_reduce(float v) {
    #pragma unroll
    for (int off = 16; off > 0; off >>= 1)
        v += __shfl_xor_sync(0xFFFFFFFFu, v, off);
    __shared__ float warp_sums[8];
    int lane = threadIdx.x & 31;
    int wid  = threadIdx.x >> 5;
    if (lane == 0) warp_sums[wid] = v;
    __syncthreads();
    float s = 0.0f;
    if (wid == 0) {
        s = (lane < (THREADS >> 5)) ? warp_sums[lane] : 0.0f;
        #pragma unroll
        for (int off = 4; off > 0; off >>= 1)
            s += __shfl_xor_sync(0xFFFFFFFFu, s, off);
    }
    __syncthreads();
    return s;
}

__global__ void __launch_bounds__(THREADS)
main_kernel(const float2* __restrict__ pts,
            const float* __restrict__ pij,
            const int* __restrict__ ei,
            const int* __restrict__ ej,
            int n_edges,
            float* __restrict__ out) {
    int bid = blockIdx.x;
    int tid = threadIdx.x;

    // ---------------- pair phase: tile (a, b) ----------------
    // i in [1024a, 1024a+1024), j in [32b, 32b+32), b >= 32a.
    int rem = bid, a = 0;
    while (rem >= NJC - 32 * a) { rem -= NJC - 32 * a; a++; }
    int b = 32 * a + rem;
    bool masked = (b < 32 * (a + 1));

    // j-features, pre-duplicated for packed math:
    //   featA[j] = { pack2(fx,fx), pack2(fy,fy) }  (one LDS.128)
    //   featZ[j] =   pack2(fz,fz)                  (one LDS.64)
    __shared__ ulonglong2 featA[TJ];
    __shared__ u64        featZ[TJ];
    int jBase = b * TJ;
    if (tid < TJ) {
        float2 pj = pts[jBase + tid];
        float fx = -2.0f * pj.x;
        float fy = -2.0f * pj.y;
        float fz = fmaf(pj.x, pj.x, fmaf(pj.y, pj.y, 1.0f));
        featA[tid] = make_ulonglong2(pack2(fx, fx), pack2(fy, fy));
        featZ[tid] = pack2(fz, fz);
    }
    __syncthreads();

    // Contiguous IPT: thread owns i0 .. i0+3 (span 3 -> per-thread mask
    // classification works in diagonal tiles). 4*tid is even -> float4 OK.
    int iBase = a * TI;
    int i0 = iBase + 4 * tid;
    const float4* pts4 = reinterpret_cast<const float4*>(pts);
    float4 qa = pts4[i0 >> 1];       // points i0, i0+1
    float4 qb = pts4[(i0 >> 1) + 1]; // points i0+2, i0+3
    float px0 = qa.x, py0 = qa.y, px1 = qa.z, py1 = qa.w;
    float px2 = qb.x, py2 = qb.y, px3 = qb.z, py3 = qb.w;
    float pc0 = fmaf(px0, px0, py0 * py0);
    float pc1 = fmaf(px1, px1, py1 * py1);
    float pc2 = fmaf(px2, px2, py2 * py2);
    float pc3 = fmaf(px3, px3, py3 * py3);
    u64 xiA = pack2(px0, px1), xiB = pack2(px2, px3);
    u64 yiA = pack2(py0, py1), yiB = pack2(py2, py3);
    u64 ciA = pack2(pc0, pc1), ciB = pack2(pc2, pc3);

    float acc0 = 0.0f, acc1 = 0.0f;

    // Per-thread classification in masked tiles: fully-below runs the fast
    // loop, fully-above contributes nothing, boundary band uses sentinels.
    bool run_fast = !masked || (i0 + 3 < jBase);
    bool run_sel  = masked && !run_fast && (i0 < jBase + TJ - 1);

    if (run_fast) {
        #pragma unroll
        for (int jj = 0; jj < TJ; jj++) {
            ulonglong2 fab = featA[jj];
            u64 fz2 = featZ[jj];
            u64 ddA = fma2(yiA, fab.y, fma2(xiA, fab.x, add2(fz2, ciA)));
            u64 ddB = fma2(yiB, fab.y, fma2(xiB, fab.x, add2(fz2, ciB)));
            // 4-way reciprocal merge:
            //   P = (d0*d2, d1*d3), S = (d0+d2, d1+d3)
            //   1/d0+1/d1+1/d2+1/d3 = (P.lo*S.hi + P.hi*S.lo) / (P.lo*P.hi)
            u64 S2 = add2(ddA, ddB);
            u64 P2 = mul2(ddA, ddB);
            float sLo, sHi, pLo, pHi;
            unpack2(S2, sLo, sHi);
            unpack2(P2, pLo, pHi);
            float num = fmaf(pHi, sLo, pLo * sHi);
            float den = pLo * pHi;
            if (jj & 1) acc1 = fmaf(num, frcp_approx(den), acc1);
            else        acc0 = fmaf(num, frcp_approx(den), acc0);
        }
    } else if (run_sel) {
        #pragma unroll 8
        for (int jj = 0; jj < TJ; jj++) {
            int j = jBase + jj;
            ulonglong2 fab = featA[jj];
            u64 fz2 = featZ[jj];
            u64 ddA = fma2(yiA, fab.y, fma2(xiA, fab.x, add2(fz2, ciA)));
            u64 ddB = fma2(yiB, fab.y, fma2(xiB, fab.x, add2(fz2, ciB)));
            float d0, d1, d2, d3;
            unpack2(ddA, d0, d1);
            unpack2(ddB, d2, d3);
            // 1e6 sentinel: 1e-6 per dead term (total bias ~5e-7 relative),
            // keeps the 4-term product safely inside fp32 range.
            d0 = (i0     < j) ? d0 : 1e6f;
            d1 = (i0 + 1 < j) ? d1 : 1e6f;
            d2 = (i0 + 2 < j) ? d2 : 1e6f;
            d3 = (i0 + 3 < j) ? d3 : 1e6f;
            float pLo = d0 * d2, pHi = d1 * d3;
            float sLo = d0 + d2, sHi = d1 + d3;
            float num = fmaf(pHi, sLo, pLo * sHi);
            float den = pLo * pHi;
            if (jj & 1) acc1 = fmaf(num, frcp_approx(den), acc1);
            else        acc0 = fmaf(num, frcp_approx(den), acc0);
        }
    }
    float pair_t = block_reduce(acc0 + acc1);

    // ---------------- edge phase (all blocks, grid-strided) ----------------
    float s1 = 0.0f, s2 = 0.0f;
    {
        int stride = GRID * THREADS;
        for (int e = bid * THREADS + tid; e < n_edges; e += stride) {
            int ia = ei[e];
            int ja = ej[e];
            float p = pij[e];
            float2 xa = pts[ia];
            float2 xb = pts[ja];
            float dx = xa.x - xb.x;
            float dy = xa.y - xb.y;
            float d = fmaf(dy, dy, fmaf(dx, dx, 2.0f));   // D + ||xi-xj||^2
            s1 += p * __logf(p * d);                      // p*(log p + log(2+d2))
            s2 += p;
        }
    }
    float t1 = block_reduce(s1);
    float t2 = block_reduce(s2);

    // ---------------- publish + last-block finish ----------------
    __shared__ int is_last;
    if (tid == 0) {
        g_pair_partial[bid] = (double)pair_t;
        g_s1_partial[bid]   = t1;
        g_s2_partial[bid]   = t2;
        __threadfence();
        int old = atomicAdd(&g_done, 1);
        is_last = (old == GRID - 1);
    }
    __syncthreads();

    if (is_last) {
        __threadfence();
        double ps = 0.0;
        float f1 = 0.0f, f2 = 0.0f;
        for (int k = tid; k < GRID; k += THREADS) {
            ps += g_pair_partial[k];
            f1 += g_s1_partial[k];
            f2 += g_s2_partial[k];
        }
        __shared__ double sd[THREADS];
        __shared__ float  sb1[THREADS];
        __shared__ float  sb2[THREADS];
        sd[tid] = ps; sb1[tid] = f1; sb2[tid] = f2;
        __syncthreads();
        for (int off = THREADS / 2; off > 0; off >>= 1) {
            if (tid < off) {
                sd[tid]  += sd[tid + off];
                sb1[tid] += sb1[tid + off];
                sb2[tid] += sb2[tid + off];
            }
            __syncthreads();
        }
        if (tid == 0) {
            double part = 2.0 * sd[0];   // diagonal cancels -n_diag exactly
            out[0] = (float)((double)sb1[0] + log(part) * (double)sb2[0]);
            g_done = 0;                  // reset for next graph replay
        }
    }
}

extern "C" void kernel_launch(void* const* d_in, const int* in_sizes, int n_in,
                              void* d_out, int out_size) {
    const float*  pij = (const float*)d_in[0];
    const int*    ei  = (const int*)d_in[1];   // jax w/o x64: int32 on device
    const int*    ej  = (const int*)d_in[2];
    const float2* pts = (const float2*)d_in[3];
    float*        out = (float*)d_out;
    int n_edges = in_sizes[0];

    main_kernel<<<GRID, THREADS>>>(pts, pij, ei, ej, n_edges, out);
}

// round 16
// speedup vs baseline: 1.0617x; 1.0617x over previous
#include <cuda_runtime.h>
#include <cuda_bf16.h>
#include <math.h>

#define N_POINTS 8192
#define TI 1024              // i-range per pair block
#define TJ 64                // j-range per pair block
#define THREADS 256
#define IPT 4                // i's per thread
#define NJC (N_POINTS / TJ)  // 128 j-chunks
#define PAIR_TILES 576       // sum_{a=0}^{7} (128 - 16a)  -> single wave (<888 resident slots)
#define GRID PAIR_TILES

typedef unsigned long long u64;

// Scratch: one slot per block + completion counter (int atomics only).
__device__ double g_pair_partial[GRID];
__device__ float  g_s1_partial[GRID];
__device__ float  g_s2_partial[GRID];
__device__ int    g_done = 0;

__device__ __forceinline__ float frcp_approx(float x) {
    float y;
    asm("rcp.approx.f32 %0, %1;" : "=f"(y) : "f"(x));
    return y;
}

// ---- packed f32x2 helpers (sm_103a; PTX-only, ptxas won't auto-fuse) ----
__device__ __forceinline__ u64 pack2(float lo, float hi) {
    u64 r; asm("mov.b64 %0, {%1, %2};" : "=l"(r) : "f"(lo), "f"(hi)); return r;
}
__device__ __forceinline__ void unpack2(u64 v, float& lo, float& hi) {
    asm("mov.b64 {%0, %1}, %2;" : "=f"(lo), "=f"(hi) : "l"(v));
}
__device__ __forceinline__ u64 fma2(u64 a, u64 b, u64 c) {
    u64 d; asm("fma.rn.f32x2 %0, %1, %2, %3;" : "=l"(d) : "l"(a), "l"(b), "l"(c)); return d;
}
__device__ __forceinline__ u64 add2(u64 a, u64 b) {
    u64 d; asm("add.rn.f32x2 %0, %1, %2;" : "=l"(d) : "l"(a), "l"(b)); return d;
}
__device__ __forceinline__ u64 mul2(u64 a, u64 b) {
    u64 d; asm("mul.rn.f32x2 %0, %1, %2;" : "=l"(d) : "l"(a), "l"(b)); return d;
}

// Block reduce; full sum valid on thread 0 only. All threads must call.
__device__ __forceinline__ float block_reduce(float v) {
    #pragma unroll
    for (int off = 16; off > 0; off >>= 1)
        v += __shfl_xor_sync(0xFFFFFFFFu, v, off);
    __shared__ float warp_sums[8];
    int lane = threadIdx.x & 31;
    int wid  = threadIdx.x >> 5;
    if (lane == 0) warp_sums[wid] = v;
    __syncthreads();
    float s = 0.0f;
    if (wid == 0) {
        s = (lane < (THREADS >> 5)) ? warp_sums[lane] : 0.0f;
        #pragma unroll
        for (int off = 4; off > 0; off >>= 1)
            s += __shfl_xor_sync(0xFFFFFFFFu, s, off);
    }
    __syncthreads();
    return s;
}

__global__ void __launch_bounds__(THREADS)
main_kernel(const float2* __restrict__ pts,
            const float* __restrict__ pij,
            const int* __restrict__ ei,
            const int* __restrict__ ej,
            int n_edges,
            float* __restrict__ out) {
    int bid = blockIdx.x;
    int tid = threadIdx.x;

    // ---------------- pair phase: tile (a, b) ----------------
    // i in [1024a, 1024a+1024), j in [64b, 64b+64), b >= 16a.
    int rem = bid, a = 0;
    while (rem >= NJC - 16 * a) { rem -= NJC - 16 * a; a++; }
    int b = 16 * a + rem;
    bool masked = (b < 16 * (a + 1));

    // j-features, pre-duplicated for packed math:
    //   featA[j] = { pack2(fx,fx), pack2(fy,fy) }  (one LDS.128)
    //   featZ[j] =   pack2(fz,fz)                  (one LDS.64)
    __shared__ ulonglong2 featA[TJ];
    __shared__ u64        featZ[TJ];
    int jBase = b * TJ;
    if (tid < TJ) {
        float2 pj = pts[jBase + tid];
        float fx = -2.0f * pj.x;
        float fy = -2.0f * pj.y;
        float fz = fmaf(pj.x, pj.x, fmaf(pj.y, pj.y, 1.0f));
        featA[tid] = make_ulonglong2(pack2(fx, fx), pack2(fy, fy));
        featZ[tid] = pack2(fz, fz);
    }
    __syncthreads();

    int iBase = a * TI;
    float px[IPT], py[IPT], pc[IPT];
    int   ii[IPT];
    #pragma unroll
    for (int k = 0; k < IPT; k++) {
        int i = iBase + tid + THREADS * k;
        float2 p = pts[i];
        px[k] = p.x; py[k] = p.y;
        pc[k] = fmaf(p.x, p.x, p.y * p.y);
        ii[k] = i;
    }
    u64 xiA = pack2(px[0], px[1]), xiB = pack2(px[2], px[3]);
    u64 yiA = pack2(py[0], py[1]), yiB = pack2(py[2], py[3]);
    u64 ciA = pack2(pc[0], pc[1]), ciB = pack2(pc[2], pc[3]);

    float acc0 = 0.0f, acc1 = 0.0f;
    if (!masked) {
        #pragma unroll 16
        for (int jj = 0; jj < TJ; jj++) {
            ulonglong2 fab = featA[jj];
            u64 fz2 = featZ[jj];
            u64 ddA = fma2(yiA, fab.y, fma2(xiA, fab.x, add2(fz2, ciA)));
            u64 ddB = fma2(yiB, fab.y, fma2(xiB, fab.x, add2(fz2, ciB)));
            // 4-way reciprocal merge:
            //   P = (d0*d2, d1*d3), S = (d0+d2, d1+d3)
            //   1/d0+1/d1+1/d2+1/d3 = (P.lo*S.hi + P.hi*S.lo) / (P.lo*P.hi)
            u64 S2 = add2(ddA, ddB);
            u64 P2 = mul2(ddA, ddB);
            float sLo, sHi, pLo, pHi;
            unpack2(S2, sLo, sHi);
            unpack2(P2, pLo, pHi);
            float num = fmaf(pHi, sLo, pLo * sHi);
            float den = pLo * pHi;
            if (jj & 1) acc1 = fmaf(num, frcp_approx(den), acc1);
            else        acc0 = fmaf(num, frcp_approx(den), acc0);
        }
    } else {
        #pragma unroll 8
        for (int jj = 0; jj < TJ; jj++) {
            int j = jBase + jj;
            ulonglong2 fab = featA[jj];
            u64 fz2 = featZ[jj];
            u64 ddA = fma2(yiA, fab.y, fma2(xiA, fab.x, add2(fz2, ciA)));
            u64 ddB = fma2(yiB, fab.y, fma2(xiB, fab.x, add2(fz2, ciB)));
            float d0, d1, d2, d3;
            unpack2(ddA, d0, d1);
            unpack2(ddB, d2, d3);
            // 1e6 sentinel: 1e-6 per dead term (total bias ~5e-7 relative on
            // part), keeps the 4-term product safely inside fp32 range.
            d0 = (ii[0] < j) ? d0 : 1e6f;
            d1 = (ii[1] < j) ? d1 : 1e6f;
            d2 = (ii[2] < j) ? d2 : 1e6f;
            d3 = (ii[3] < j) ? d3 : 1e6f;
            float pLo = d0 * d2, pHi = d1 * d3;
            float sLo = d0 + d2, sHi = d1 + d3;
            float num = fmaf(pHi, sLo, pLo * sHi);
            float den = pLo * pHi;
            if (jj & 1) acc1 = fmaf(num, frcp_approx(den), acc1);
            else        acc0 = fmaf(num, frcp_approx(den), acc0);
        }
    }
    float pair_t = block_reduce(acc0 + acc1);

    // ---------------- edge phase (all blocks, grid-strided) ----------------
    float s1 = 0.0f, s2 = 0.0f;
    {
        int stride = GRID * THREADS;
        for (int e = bid * THREADS + tid; e < n_edges; e += stride) {
            int ia = ei[e];
            int ja = ej[e];
            float p = pij[e];
            float2 xa = pts[ia];
            float2 xb = pts[ja];
            float dx = xa.x - xb.x;
            float dy = xa.y - xb.y;
            float d = fmaf(dy, dy, fmaf(dx, dx, 2.0f));   // D + ||xi-xj||^2
            s1 += p * __logf(p * d);                      // p*(log p + log(2+d2))
            s2 += p;
        }
    }
    float t1 = block_reduce(s1);
    float t2 = block_reduce(s2);

    // ---------------- publish + last-block finish ----------------
    __shared__ int is_last;
    if (tid == 0) {
        g_pair_partial[bid] = (double)pair_t;
        g_s1_partial[bid]   = t1;
        g_s2_partial[bid]   = t2;
        __threadfence();
        int old = atomicAdd(&g_done, 1);
        is_last = (old == GRID - 1);
    }
    __syncthreads();

    if (is_last) {
        __threadfence();
        double ps = 0.0;
        float f1 = 0.0f, f2 = 0.0f;
        for (int k = tid; k < GRID; k += THREADS) {
            ps += g_pair_partial[k];
            f1 += g_s1_partial[k];
            f2 += g_s2_partial[k];
        }
        __shared__ double sd[THREADS];
        __shared__ float  sb1[THREADS];
        __shared__ float  sb2[THREADS];
        sd[tid] = ps; sb1[tid] = f1; sb2[tid] = f2;
        __syncthreads();
        for (int off = THREADS / 2; off > 0; off >>= 1) {
            if (tid < off) {
                sd[tid]  += sd[tid + off];
                sb1[tid] += sb1[tid + off];
                sb2[tid] += sb2[tid + off];
            }
            __syncthreads();
        }
        if (tid == 0) {
            double part = 2.0 * sd[0];   // diagonal cancels -n_diag exactly
            out[0] = (float)((double)sb1[0] + log(part) * (double)sb2[0]);
            g_done = 0;                  // reset for next graph replay
        }
    }
}

extern "C" void kernel_launch(void* const* d_in, const int* in_sizes, int n_in,
                              void* d_out, int out_size) {
    const float*  pij = (const float*)d_in[0];
    const int*    ei  = (const int*)d_in[1];   // jax w/o x64: int32 on device
    const int*    ej  = (const int*)d_in[2];
    const float2* pts = (const float2*)d_in[3];
    float*        out = (float*)d_out;
    int n_edges = in_sizes[0];

    main_kernel<<<GRID, THREADS>>>(pts, pij, ei, ej, n_edges, out);
}

// round 17
// speedup vs baseline: 1.0964x; 1.0327x over previous
#include <cuda_runtime.h>
#include <cuda_bf16.h>
#include <math.h>

#define N_POINTS 8192
#define TI 1024              // i-range per pair block
#define TJ 64                // j-range per pair block (32 j-pairs)
#define NJP (TJ / 2)
#define THREADS 256
#define IPT 4                // i's per thread (strided)
#define NJC (N_POINTS / TJ)  // 128 j-chunks
#define PAIR_TILES 576       // sum_{a=0}^{7} (128 - 16a)  -> single wave
#define GRID PAIR_TILES

typedef unsigned long long u64;

// Scratch: one slot per block + completion counter (int atomics only).
__device__ double g_pair_partial[GRID];
__device__ float  g_s1_partial[GRID];
__device__ float  g_s2_partial[GRID];
__device__ int    g_done = 0;

__device__ __forceinline__ float frcp_approx(float x) {
    float y;
    asm("rcp.approx.f32 %0, %1;" : "=f"(y) : "f"(x));
    return y;
}

// ---- packed f32x2 helpers (sm_103a; PTX-only, ptxas won't auto-fuse) ----
__device__ __forceinline__ u64 pack2(float lo, float hi) {
    u64 r; asm("mov.b64 %0, {%1, %2};" : "=l"(r) : "f"(lo), "f"(hi)); return r;
}
__device__ __forceinline__ void unpack2(u64 v, float& lo, float& hi) {
    asm("mov.b64 {%0, %1}, %2;" : "=f"(lo), "=f"(hi) : "l"(v));
}
__device__ __forceinline__ u64 fma2(u64 a, u64 b, u64 c) {
    u64 d; asm("fma.rn.f32x2 %0, %1, %2, %3;" : "=l"(d) : "l"(a), "l"(b), "l"(c)); return d;
}
__device__ __forceinline__ u64 add2(u64 a, u64 b) {
    u64 d; asm("add.rn.f32x2 %0, %1, %2;" : "=l"(d) : "l"(a), "l"(b)); return d;
}
__device__ __forceinline__ u64 mul2(u64 a, u64 b) {
    u64 d; asm("mul.rn.f32x2 %0, %1, %2;" : "=l"(d) : "l"(a), "l"(b)); return d;
}

// Block reduce; full sum valid on thread 0 only. All threads must call.
__device__ __forceinline__ float block_reduce(float v) {
    #pragma unroll
    for (int off = 16; off > 0; off >>= 1)
        v += __shfl_xor_sync(0xFFFFFFFFu, v, off);
    __shared__ float warp_sums[8];
    int lane = threadIdx.x & 31;
    int wid  = threadIdx.x >> 5;
    if (lane == 0) warp_sums[wid] = v;
    __syncthreads();
    float s = 0.0f;
    if (wid == 0) {
        s = (lane < (THREADS >> 5)) ? warp_sums[lane] : 0.0f;
        #pragma unroll
        for (int off = 4; off > 0; off >>= 1)
            s += __shfl_xor_sync(0xFFFFFFFFu, s, off);
    }
    __syncthreads();
    return s;
}

__global__ void __launch_bounds__(THREADS)
main_kernel(const float2* __restrict__ pts,
            const float* __restrict__ pij,
            const int* __restrict__ ei,
            const int* __restrict__ ej,
            int n_edges,
            float* __restrict__ out) {
    int bid = blockIdx.x;
    int tid = threadIdx.x;

    // ---------------- pair phase: tile (a, b) ----------------
    // i in [1024a, 1024a+1024), j in [64b, 64b+64), b >= 16a.
    int rem = bid, a = 0;
    while (rem >= NJC - 16 * a) { rem -= NJC - 16 * a; a++; }
    int b = 16 * a + rem;
    bool masked = (b < 16 * (a + 1));

    // j-PAIR features: lane pair (j0=2jp, j1=2jp+1).
    //   featXY[jp] = { (fx_j0,fx_j1), (fy_j0,fy_j1) }  (one LDS.128)
    //   featZ [jp] =   (fz_j0,fz_j1)                   (one LDS.64)
    __shared__ ulonglong2 featXY[NJP];
    __shared__ u64        featZ[NJP];
    int jBase = b * TJ;
    if (tid < NJP) {
        const float4* p4 = reinterpret_cast<const float4*>(pts);
        float4 q = p4[(jBase >> 1) + tid];      // points j0=jBase+2tid, j1=+1
        float fx0 = -2.0f * q.x, fy0 = -2.0f * q.y;
        float fz0 = fmaf(q.x, q.x, fmaf(q.y, q.y, 1.0f));
        float fx1 = -2.0f * q.z, fy1 = -2.0f * q.w;
        float fz1 = fmaf(q.z, q.z, fmaf(q.w, q.w, 1.0f));
        featXY[tid] = make_ulonglong2(pack2(fx0, fx1), pack2(fy0, fy1));
        featZ[tid]  = pack2(fz0, fz1);
    }
    __syncthreads();

    int iBase = a * TI;
    u64 xi2[IPT], yi2[IPT], ci2[IPT];
    int ii[IPT];
    #pragma unroll
    for (int k = 0; k < IPT; k++) {
        int i = iBase + tid + THREADS * k;
        float2 p = pts[i];
        float c = fmaf(p.x, p.x, p.y * p.y);
        xi2[k] = pack2(p.x, p.x);
        yi2[k] = pack2(p.y, p.y);
        ci2[k] = pack2(c, c);
        ii[k] = i;
    }

    float acc0 = 0.0f, acc1 = 0.0f;
    if (!masked) {
        #pragma unroll
        for (int jp = 0; jp < NJP; jp++) {
            ulonglong2 fxy = featXY[jp];
            u64 fz2 = featZ[jp];
            // dd_k lanes = (d_{ik,j0}, d_{ik,j1})
            u64 dd0 = fma2(yi2[0], fxy.y, fma2(xi2[0], fxy.x, add2(fz2, ci2[0])));
            u64 dd1 = fma2(yi2[1], fxy.y, fma2(xi2[1], fxy.x, add2(fz2, ci2[1])));
            u64 dd2 = fma2(yi2[2], fxy.y, fma2(xi2[2], fxy.x, add2(fz2, ci2[2])));
            u64 dd3 = fma2(yi2[3], fxy.y, fma2(xi2[3], fxy.x, add2(fz2, ci2[3])));
            // 8-way merge: per j-lane 4-way (over i), then cross-combine over j.
            u64 S01 = add2(dd0, dd1), P01 = mul2(dd0, dd1);
            u64 S23 = add2(dd2, dd3), P23 = mul2(dd2, dd3);
            u64 n2 = fma2(S01, P23, mul2(S23, P01));   // per-lane numerator
            u64 d2v = mul2(P01, P23);                  // per-lane denominator
            float nLo, nHi, dLo, dHi;
            unpack2(n2, nLo, nHi);
            unpack2(d2v, dLo, dHi);
            float num = fmaf(nLo, dHi, nHi * dLo);
            float den = dLo * dHi;                     // product of 8 d's (<~1e13)
            if (jp & 1) acc1 = fmaf(num, frcp_approx(den), acc1);
            else        acc0 = fmaf(num, frcp_approx(den), acc0);
        }
    } else {
        #pragma unroll 8
        for (int jp = 0; jp < NJP; jp++) {
            int j0 = jBase + 2 * jp, j1 = j0 + 1;
            ulonglong2 fxy = featXY[jp];
            u64 fz2 = featZ[jp];
            u64 dd0 = fma2(yi2[0], fxy.y, fma2(xi2[0], fxy.x, add2(fz2, ci2[0])));
            u64 dd1 = fma2(yi2[1], fxy.y, fma2(xi2[1], fxy.x, add2(fz2, ci2[1])));
            u64 dd2 = fma2(yi2[2], fxy.y, fma2(xi2[2], fxy.x, add2(fz2, ci2[2])));
            u64 dd3 = fma2(yi2[3], fxy.y, fma2(xi2[3], fxy.x, add2(fz2, ci2[3])));
            float dA0, dA1, dB0, dB1, dC0, dC1, dD0, dD1;
            unpack2(dd0, dA0, dA1);
            unpack2(dd1, dB0, dB1);
            unpack2(dd2, dC0, dC1);
            unpack2(dd3, dD0, dD1);
            // 1e6 sentinel: 1e-6 per dead term (bias ~5e-7 relative on part);
            // per-j 4-term product <= 1e24, inside fp32 range.
            dA0 = (ii[0] < j0) ? dA0 : 1e6f;  dA1 = (ii[0] < j1) ? dA1 : 1e6f;
            dB0 = (ii[1] < j0) ? dB0 : 1e6f;  dB1 = (ii[1] < j1) ? dB1 : 1e6f;
            dC0 = (ii[2] < j0) ? dC0 : 1e6f;  dC1 = (ii[2] < j1) ? dC1 : 1e6f;
            dD0 = (ii[3] < j0) ? dD0 : 1e6f;  dD1 = (ii[3] < j1) ? dD1 : 1e6f;
            // scalar 4-way merge per j-lane
            float pL0 = dA0 * dC0, pH0 = dB0 * dD0;
            float sL0 = dA0 + dC0, sH0 = dB0 + dD0;
            float num0 = fmaf(pH0, sL0, pL0 * sH0);
            float den0 = pL0 * pH0;
            acc0 = fmaf(num0, frcp_approx(den0), acc0);
            float pL1 = dA1 * dC1, pH1 = dB1 * dD1;
            float sL1 = dA1 + dC1, sH1 = dB1 + dD1;
            float num1 = fmaf(pH1, sL1, pL1 * sH1);
            float den1 = pL1 * pH1;
            acc1 = fmaf(num1, frcp_approx(den1), acc1);
        }
    }
    float pair_t = block_reduce(acc0 + acc1);

    // ---------------- edge phase (all blocks, grid-strided) ----------------
    float s1 = 0.0f, s2 = 0.0f;
    {
        int stride = GRID * THREADS;
        for (int e = bid * THREADS + tid; e < n_edges; e += stride) {
            int ia = ei[e];
            int ja = ej[e];
            float p = pij[e];
            float2 xa = pts[ia];
            float2 xb = pts[ja];
            float dx = xa.x - xb.x;
            float dy = xa.y - xb.y;
            float d = fmaf(dy, dy, fmaf(dx, dx, 2.0f));   // D + ||xi-xj||^2
            s1 += p * __logf(p * d);                      // p*(log p + log(2+d2))
            s2 += p;
        }
    }
    float t1 = block_reduce(s1);
    float t2 = block_reduce(s2);

    // ---------------- publish + last-block finish ----------------
    __shared__ int is_last;
    if (tid == 0) {
        g_pair_partial[bid] = (double)pair_t;
        g_s1_partial[bid]   = t1;
        g_s2_partial[bid]   = t2;
        __threadfence();
        int old = atomicAdd(&g_done, 1);
        is_last = (old == GRID - 1);
    }
    __syncthreads();

    if (is_last) {
        __threadfence();
        double ps = 0.0;
        float f1 = 0.0f, f2 = 0.0f;
        for (int k = tid; k < GRID; k += THREADS) {
            ps += g_pair_partial[k];
            f1 += g_s1_partial[k];
            f2 += g_s2_partial[k];
        }
        __shared__ double sd[THREADS];
        __shared__ float  sb1[THREADS];
        __shared__ float  sb2[THREADS];
        sd[tid] = ps; sb1[tid] = f1; sb2[tid] = f2;
        __syncthreads();
        for (int off = THREADS / 2; off > 0; off >>= 1) {
            if (tid < off) {
                sd[tid]  += sd[tid + off];
                sb1[tid] += sb1[tid + off];
                sb2[tid] += sb2[tid + off];
            }
            __syncthreads();
        }
        if (tid == 0) {
            double part = 2.0 * sd[0];   // diagonal cancels -n_diag exactly
            out[0] = (float)((double)sb1[0] + log(part) * (double)sb2[0]);
            g_done = 0;                  // reset for next graph replay
        }
    }
}

extern "C" void kernel_launch(void* const* d_in, const int* in_sizes, int n_in,
                              void* d_out, int out_size) {
    const float*  pij = (const float*)d_in[0];
    const int*    ei  = (const int*)d_in[1];   // jax w/o x64: int32 on device
    const int*    ej  = (const int*)d_in[2];
    const float2* pts = (const float2*)d_in[3];
    float*        out = (float*)d_out;
    int n_edges = in_sizes[0];

    main_kernel<<<GRID, THREADS>>>(pts, pij, ei, ej, n_edges, out);
}